// round 3
// baseline (speedup 1.0000x reference)
#include <cuda_runtime.h>
#include <cstdint>

#define NN 16384
#define NH 128
#define NE (NN*32)

// ---------------- device scratch (allocation-free rule: __device__ globals) ----
__device__ __align__(16) float g_deg[NN];
__device__ __align__(16) float g_dinv[NN];
__device__ __align__(16) float g_h[NN*NH];     // x @ W
__device__ __align__(16) float g_agg[NN*NH];   // scatter accumulator
__device__ __align__(16) float g_h2[NN*NH];    // relu(gcn), rounded to tf32

// ---------------- stage 1: init (must re-run every launch) ----------------
__global__ void k_init(){
    int i = blockIdx.x * blockDim.x + threadIdx.x;
    if (i < NN*NH) g_agg[i] = 0.0f;
    if (i < NN)    g_deg[i] = 1.0f;   // self-loop
}

// ---------------- stage 2: degree (edge_index is int32: JAX x64 disabled) ---
__global__ void k_degree(const int* __restrict__ ei){
    int e = blockIdx.x * blockDim.x + threadIdx.x;
    if (e >= NE) return;
    int c = ei[NE + e];
    atomicAdd(&g_deg[c], 1.0f);
}

// ---------------- stage 3: dinv ----------------
__global__ void k_dinv(){
    int i = blockIdx.x * blockDim.x + threadIdx.x;
    if (i < NN) g_dinv[i] = rsqrtf(g_deg[i]);   // deg >= 1 always
}

// ---------------- stage 4: h = x @ W ----------------
#define XW_ROWS 32
__global__ void k_xw(const float* __restrict__ x, const float* __restrict__ W){
    extern __shared__ float sm[];
    float* Ws = sm;                 // 128*128
    float* xs = sm + NH*NH;         // XW_ROWS*128
    int tid  = threadIdx.x;         // 128 threads; tid == output column
    int row0 = blockIdx.x * XW_ROWS;
    for (int i = tid; i < NH*NH; i += 128) Ws[i] = W[i];
    for (int i = tid; i < XW_ROWS*NH; i += 128) xs[i] = x[(size_t)row0*NH + i];
    __syncthreads();
    float acc[XW_ROWS];
#pragma unroll
    for (int r = 0; r < XW_ROWS; r++) acc[r] = 0.0f;
    for (int k = 0; k < NH; k++){
        float wv = Ws[k*NH + tid];
#pragma unroll
        for (int r = 0; r < XW_ROWS; r++) acc[r] += xs[r*NH + k] * wv;
    }
#pragma unroll
    for (int r = 0; r < XW_ROWS; r++) g_h[(size_t)(row0 + r)*NH + tid] = acc[r];
}

// ---------------- stage 5: edge scatter (warp per edge, float4 atomics) -----
__global__ void k_scatter(const int* __restrict__ ei){
    int g = blockIdx.x * blockDim.x + threadIdx.x;
    int e = g >> 5;
    if (e >= NE) return;
    int lane = g & 31;
    int r = ei[e];
    int c = ei[NE + e];
    float nrm = g_dinv[r] * g_dinv[c];
    float4 hv = *reinterpret_cast<const float4*>(g_h + (size_t)r*NH + lane*4);
    float4 v = make_float4(nrm*hv.x, nrm*hv.y, nrm*hv.z, nrm*hv.w);
    atomicAdd(reinterpret_cast<float4*>(g_agg + (size_t)c*NH + lane*4), v);
}

// ---------------- stage 6: self-loop + bias + relu + tf32 round -------------
__global__ void k_final(const float* __restrict__ b){
    int i = blockIdx.x * blockDim.x + threadIdx.x;
    if (i >= NN*NH) return;
    int n = i >> 7, c = i & 127;
    float di = g_dinv[n];
    float v = g_agg[i] + di*di*g_h[i] + b[c];
    v = v > 0.0f ? v : 0.0f;
    uint32_t t;
    asm("cvt.rna.tf32.f32 %0, %1;" : "=r"(t) : "f"(v));
    g_h2[i] = __uint_as_float(t);
}

// ---------------- stage 7: C = H @ H^T via mma.sync tf32 --------------------
// CTA tile 128x128, 256 threads, warp grid 2(m) x 4(n), warp tile 64x32.
// K=128 in two 64-deep smem chunks. Smem row stride 68 floats -> bank pattern
// (4g + c) mod 32 is a bijection over lanes => conflict-free fragment loads.
#define KC 64
#define LDSW 68   // floats per smem row

__device__ __forceinline__ void mma_tf32(float* d,
        uint32_t a0, uint32_t a1, uint32_t a2, uint32_t a3,
        uint32_t b0, uint32_t b1){
    asm volatile(
        "mma.sync.aligned.m16n8k8.row.col.f32.tf32.tf32.f32 "
        "{%0,%1,%2,%3}, {%4,%5,%6,%7}, {%8,%9}, {%0,%1,%2,%3};"
        : "+f"(d[0]), "+f"(d[1]), "+f"(d[2]), "+f"(d[3])
        : "r"(a0), "r"(a1), "r"(a2), "r"(a3), "r"(b0), "r"(b1));
}

__global__ void __launch_bounds__(256, 2) k_gemm(float* __restrict__ out){
    extern __shared__ float sm[];
    float* As = sm;                  // 128 x LDSW
    float* Bs = sm + 128*LDSW;       // 128 x LDSW

    int tid  = threadIdx.x;
    int lane = tid & 31;
    int wid  = tid >> 5;
    int wm   = wid >> 2;             // 0..1
    int wn   = wid & 3;              // 0..3
    int m0w  = wm * 64;
    int n0w  = wn * 32;
    int tm   = blockIdx.x >> 7;
    int tn   = blockIdx.x & 127;

    const float* Ag = g_h2 + (size_t)tm * 128 * NH;
    const float* Bg = g_h2 + (size_t)tn * 128 * NH;

    float acc[4][4][4];
#pragma unroll
    for (int i = 0; i < 4; i++)
#pragma unroll
        for (int j = 0; j < 4; j++)
#pragma unroll
            for (int q = 0; q < 4; q++) acc[i][j][q] = 0.0f;

    int grp = lane >> 2;             // 0..7
    int qc  = lane & 3;              // 0..3

    for (int kc = 0; kc < 2; ++kc){
        if (kc) __syncthreads();     // protect smem reuse
        // global -> smem: 128 rows x 16 float4 per tile, 8 per thread
#pragma unroll
        for (int i = 0; i < 8; ++i){
            int idx = i*256 + tid;
            int r = idx >> 4, c4 = idx & 15;
            float4 va = *reinterpret_cast<const float4*>(Ag + r*NH + kc*KC + c4*4);
            float4 vb = *reinterpret_cast<const float4*>(Bg + r*NH + kc*KC + c4*4);
            *reinterpret_cast<float4*>(As + r*LDSW + c4*4) = va;
            *reinterpret_cast<float4*>(Bs + r*LDSW + c4*4) = vb;
        }
        __syncthreads();

#pragma unroll
        for (int k8 = 0; k8 < KC/8; ++k8){
            int kb = k8*8;
            uint32_t a[4][4], b[4][2];
#pragma unroll
            for (int mf = 0; mf < 4; ++mf){
                int r0 = m0w + mf*16 + grp;
                a[mf][0] = __float_as_uint(As[r0*LDSW     + kb + qc]);
                a[mf][1] = __float_as_uint(As[(r0+8)*LDSW + kb + qc]);
                a[mf][2] = __float_as_uint(As[r0*LDSW     + kb + qc + 4]);
                a[mf][3] = __float_as_uint(As[(r0+8)*LDSW + kb + qc + 4]);
            }
#pragma unroll
            for (int nf = 0; nf < 4; ++nf){
                int rn = n0w + nf*8 + grp;
                b[nf][0] = __float_as_uint(Bs[rn*LDSW + kb + qc]);
                b[nf][1] = __float_as_uint(Bs[rn*LDSW + kb + qc + 4]);
            }
#pragma unroll
            for (int mf = 0; mf < 4; ++mf)
#pragma unroll
                for (int nf = 0; nf < 4; ++nf)
                    mma_tf32(acc[mf][nf], a[mf][0], a[mf][1], a[mf][2], a[mf][3],
                             b[nf][0], b[nf][1]);
        }
    }

    // epilogue: c0,c1 at (row, 2q), (row, 2q+1); c2,c3 at row+8
    float* outB = out + (size_t)(tm*128) * NN + (size_t)(tn*128);
#pragma unroll
    for (int mf = 0; mf < 4; ++mf){
#pragma unroll
        for (int nf = 0; nf < 4; ++nf){
            int r = m0w + mf*16 + grp;
            int c = n0w + nf*8 + 2*qc;
            *reinterpret_cast<float2*>(outB + (size_t)r*NN + c) =
                make_float2(acc[mf][nf][0], acc[mf][nf][1]);
            *reinterpret_cast<float2*>(outB + (size_t)(r+8)*NN + c) =
                make_float2(acc[mf][nf][2], acc[mf][nf][3]);
        }
    }
}

// ---------------- launcher ----------------
extern "C" void kernel_launch(void* const* d_in, const int* in_sizes, int n_in,
                              void* d_out, int out_size){
    const float* x  = (const float*)d_in[0];
    const int*   ei = (const int*)d_in[1];
    const float* W  = (const float*)d_in[2];
    const float* b  = (const float*)d_in[3];
    float*       out = (float*)d_out;

    cudaFuncSetAttribute(k_xw,   cudaFuncAttributeMaxDynamicSharedMemorySize, 81920);
    cudaFuncSetAttribute(k_gemm, cudaFuncAttributeMaxDynamicSharedMemorySize, 2*128*LDSW*4);

    k_init   <<<(NN*NH + 255)/256, 256>>>();
    k_degree <<<(NE + 255)/256, 256>>>(ei);
    k_dinv   <<<(NN + 255)/256, 256>>>();
    k_xw     <<<NN/XW_ROWS, 128, 81920>>>(x, W);
    k_scatter<<<(NE*32)/256, 256>>>(ei);
    k_final  <<<(NN*NH + 255)/256, 256>>>(b);
    k_gemm   <<<16384, 256, 2*128*LDSW*4>>>(out);
}

// round 4
// speedup vs baseline: 2.1874x; 2.1874x over previous
#include <cuda_runtime.h>
#include <cstdint>

#define NN 16384
#define NH 128
#define NE (NN*32)

// ---------------- device scratch (allocation-free rule: __device__ globals) ----
__device__ __align__(16) float g_deg[NN];
__device__ __align__(16) float g_dinv[NN];
__device__ __align__(16) float g_h[NN*NH];     // x @ W (tf32 mma)
__device__ __align__(16) float g_agg[NN*NH];   // scatter accumulator
__device__ __align__(16) float g_h2[NN*NH];    // relu(gcn), rounded to tf32

#define KC 64
#define LDSW 68    // floats per smem row in mainloop tiles (conflict-free frag loads)
#define TPAD 129   // transpose staging stride: (129c + r)%32 = (c+r)%32 -> CF column reads

__device__ __forceinline__ float tf32r(float v){
    uint32_t t; asm("cvt.rna.tf32.f32 %0, %1;" : "=r"(t) : "f"(v));
    return __uint_as_float(t);
}

__device__ __forceinline__ void mma_tf32(float* d,
        uint32_t a0, uint32_t a1, uint32_t a2, uint32_t a3,
        uint32_t b0, uint32_t b1){
    asm volatile(
        "mma.sync.aligned.m16n8k8.row.col.f32.tf32.tf32.f32 "
        "{%0,%1,%2,%3}, {%4,%5,%6,%7}, {%8,%9}, {%0,%1,%2,%3};"
        : "+f"(d[0]), "+f"(d[1]), "+f"(d[2]), "+f"(d[3])
        : "r"(a0), "r"(a1), "r"(a2), "r"(a3), "r"(b0), "r"(b1));
}

// ---------------- stage 1: init ----------------
__global__ void k_init(){
    int i = blockIdx.x * blockDim.x + threadIdx.x;
    if (i < NN*NH) g_agg[i] = 0.0f;
    if (i < NN)    g_deg[i] = 1.0f;   // self-loop
}

// ---------------- stage 2: degree (edge_index is int32) ----------------
__global__ void k_degree(const int* __restrict__ ei){
    int e = blockIdx.x * blockDim.x + threadIdx.x;
    if (e >= NE) return;
    atomicAdd(&g_deg[ei[NE + e]], 1.0f);
}

// ---------------- stage 3: dinv ----------------
__global__ void k_dinv(){
    int i = blockIdx.x * blockDim.x + threadIdx.x;
    if (i < NN) g_dinv[i] = rsqrtf(g_deg[i]);
}

// ---------------- stage 4: h = x @ W via tf32 mma ----------------
// CTA: 128 rows of x, full 128 output cols. 256 thr, warp grid 2x4, warp tile 64x32.
__global__ void __launch_bounds__(256, 2) k_xw(const float* __restrict__ x,
                                               const float* __restrict__ W){
    extern __shared__ float sm[];
    float* As = sm;                  // 128 x LDSW
    float* Bs = sm + 128*LDSW;       // 128(n) x LDSW(k)  == W^T chunk

    int tid  = threadIdx.x;
    int lane = tid & 31;
    int wid  = tid >> 5;
    int m0w  = (wid >> 2) * 64;
    int n0w  = (wid & 3) * 32;
    int row0 = blockIdx.x * 128;
    int grp  = lane >> 2, qc = lane & 3;

    float acc[4][4][4];
#pragma unroll
    for (int i = 0; i < 4; i++)
#pragma unroll
        for (int j = 0; j < 4; j++)
#pragma unroll
            for (int q = 0; q < 4; q++) acc[i][j][q] = 0.0f;

    for (int kc = 0; kc < 2; ++kc){
        if (kc) __syncthreads();
        // A: x rows (coalesced), rounded to tf32
#pragma unroll
        for (int i = 0; i < 8; ++i){
            int idx = i*256 + tid;
            int r = idx >> 4, c4 = idx & 15;
            float4 v = *reinterpret_cast<const float4*>(x + (size_t)(row0 + r)*NH + kc*KC + c4*4);
            v.x = tf32r(v.x); v.y = tf32r(v.y); v.z = tf32r(v.z); v.w = tf32r(v.w);
            *reinterpret_cast<float4*>(As + r*LDSW + c4*4) = v;
        }
        // B: W^T  (Bs[n][kk] = W[kc*64+kk][n]); coalesced gather over n
#pragma unroll
        for (int i = 0; i < 8; ++i){
            int idx = i*256 + tid;
            int n = idx & 127, kk4 = idx >> 7;   // kk4: 0..15
            float4 v;
            v.x = tf32r(W[(size_t)(kc*KC + kk4*4 + 0)*NH + n]);
            v.y = tf32r(W[(size_t)(kc*KC + kk4*4 + 1)*NH + n]);
            v.z = tf32r(W[(size_t)(kc*KC + kk4*4 + 2)*NH + n]);
            v.w = tf32r(W[(size_t)(kc*KC + kk4*4 + 3)*NH + n]);
            *reinterpret_cast<float4*>(Bs + n*LDSW + kk4*4) = v;
        }
        __syncthreads();

#pragma unroll
        for (int k8 = 0; k8 < KC/8; ++k8){
            int kb = k8*8;
            uint32_t a[4][4], b[4][2];
#pragma unroll
            for (int mf = 0; mf < 4; ++mf){
                int r0 = m0w + mf*16 + grp;
                a[mf][0] = __float_as_uint(As[r0*LDSW     + kb + qc]);
                a[mf][1] = __float_as_uint(As[(r0+8)*LDSW + kb + qc]);
                a[mf][2] = __float_as_uint(As[r0*LDSW     + kb + qc + 4]);
                a[mf][3] = __float_as_uint(As[(r0+8)*LDSW + kb + qc + 4]);
            }
#pragma unroll
            for (int nf = 0; nf < 4; ++nf){
                int rn = n0w + nf*8 + grp;
                b[nf][0] = __float_as_uint(Bs[rn*LDSW + kb + qc]);
                b[nf][1] = __float_as_uint(Bs[rn*LDSW + kb + qc + 4]);
            }
#pragma unroll
            for (int mf = 0; mf < 4; ++mf)
#pragma unroll
                for (int nf = 0; nf < 4; ++nf)
                    mma_tf32(acc[mf][nf], a[mf][0], a[mf][1], a[mf][2], a[mf][3],
                             b[nf][0], b[nf][1]);
        }
    }

#pragma unroll
    for (int mf = 0; mf < 4; ++mf)
#pragma unroll
        for (int nf = 0; nf < 4; ++nf){
            int r = m0w + mf*16 + grp;
            int c = n0w + nf*8 + 2*qc;
            *reinterpret_cast<float2*>(g_h + (size_t)(row0 + r)*NH + c) =
                make_float2(acc[mf][nf][0], acc[mf][nf][1]);
            *reinterpret_cast<float2*>(g_h + (size_t)(row0 + r + 8)*NH + c) =
                make_float2(acc[mf][nf][2], acc[mf][nf][3]);
        }
}

// ---------------- stage 5: edge scatter (warp per edge, float4 atomics) -----
__global__ void k_scatter(const int* __restrict__ ei){
    int g = blockIdx.x * blockDim.x + threadIdx.x;
    int e = g >> 5;
    if (e >= NE) return;
    int lane = g & 31;
    int r = ei[e];
    int c = ei[NE + e];
    float nrm = g_dinv[r] * g_dinv[c];
    float4 hv = *reinterpret_cast<const float4*>(g_h + (size_t)r*NH + lane*4);
    float4 v = make_float4(nrm*hv.x, nrm*hv.y, nrm*hv.z, nrm*hv.w);
    atomicAdd(reinterpret_cast<float4*>(g_agg + (size_t)c*NH + lane*4), v);
}

// ---------------- stage 6: self-loop + bias + relu + tf32 round -------------
__global__ void k_final(const float* __restrict__ b){
    int i = blockIdx.x * blockDim.x + threadIdx.x;
    if (i >= NN*NH) return;
    int n = i >> 7, c = i & 127;
    float di = g_dinv[n];
    float v = g_agg[i] + di*di*g_h[i] + b[c];
    g_h2[i] = tf32r(v > 0.0f ? v : 0.0f);
}

// ---------------- stage 7: C = H @ H^T, upper-triangle tiles only -----------
#define NTILES 8256   // 128*129/2

__global__ void __launch_bounds__(256, 2) k_gemm(float* __restrict__ out){
    extern __shared__ float sm[];
    float* As = sm;                  // 128 x LDSW
    float* Bs = sm + 128*LDSW;       // 128 x LDSW

    int tid  = threadIdx.x;
    int lane = tid & 31;
    int wid  = tid >> 5;
    int m0w  = (wid >> 2) * 64;
    int n0w  = (wid & 3) * 32;
    int grp  = lane >> 2, qc = lane & 3;

    // decode upper-triangle tile index (uniform per CTA)
    int tm = 0, rem = blockIdx.x;
    while (rem >= 128 - tm){ rem -= 128 - tm; tm++; }
    int tn = tm + rem;

    const float* Ag = g_h2 + (size_t)tm * 128 * NH;
    const float* Bg = g_h2 + (size_t)tn * 128 * NH;

    float acc[4][4][4];
#pragma unroll
    for (int i = 0; i < 4; i++)
#pragma unroll
        for (int j = 0; j < 4; j++)
#pragma unroll
            for (int q = 0; q < 4; q++) acc[i][j][q] = 0.0f;

    for (int kc = 0; kc < 2; ++kc){
        if (kc) __syncthreads();
#pragma unroll
        for (int i = 0; i < 8; ++i){
            int idx = i*256 + tid;
            int r = idx >> 4, c4 = idx & 15;
            float4 va = *reinterpret_cast<const float4*>(Ag + r*NH + kc*KC + c4*4);
            float4 vb = *reinterpret_cast<const float4*>(Bg + r*NH + kc*KC + c4*4);
            *reinterpret_cast<float4*>(As + r*LDSW + c4*4) = va;
            *reinterpret_cast<float4*>(Bs + r*LDSW + c4*4) = vb;
        }
        __syncthreads();

#pragma unroll
        for (int k8 = 0; k8 < KC/8; ++k8){
            int kb = k8*8;
            uint32_t a[4][4], b[4][2];
#pragma unroll
            for (int mf = 0; mf < 4; ++mf){
                int r0 = m0w + mf*16 + grp;
                a[mf][0] = __float_as_uint(As[r0*LDSW     + kb + qc]);
                a[mf][1] = __float_as_uint(As[(r0+8)*LDSW + kb + qc]);
                a[mf][2] = __float_as_uint(As[r0*LDSW     + kb + qc + 4]);
                a[mf][3] = __float_as_uint(As[(r0+8)*LDSW + kb + qc + 4]);
            }
#pragma unroll
            for (int nf = 0; nf < 4; ++nf){
                int rn = n0w + nf*8 + grp;
                b[nf][0] = __float_as_uint(Bs[rn*LDSW + kb + qc]);
                b[nf][1] = __float_as_uint(Bs[rn*LDSW + kb + qc + 4]);
            }
#pragma unroll
            for (int mf = 0; mf < 4; ++mf)
#pragma unroll
                for (int nf = 0; nf < 4; ++nf)
                    mma_tf32(acc[mf][nf], a[mf][0], a[mf][1], a[mf][2], a[mf][3],
                             b[nf][0], b[nf][1]);
        }
    }

    // direct (coalesced) write of the (tm, tn) block
    float* outB = out + (size_t)(tm*128) * NN + (size_t)(tn*128);
#pragma unroll
    for (int mf = 0; mf < 4; ++mf)
#pragma unroll
        for (int nf = 0; nf < 4; ++nf){
            int r = m0w + mf*16 + grp;
            int c = n0w + nf*8 + 2*qc;
            *reinterpret_cast<float2*>(outB + (size_t)r*NN + c) =
                make_float2(acc[mf][nf][0], acc[mf][nf][1]);
            *reinterpret_cast<float2*>(outB + (size_t)(r+8)*NN + c) =
                make_float2(acc[mf][nf][2], acc[mf][nf][3]);
        }

    if (tm == tn) return;

    // mirrored (tn, tm) block: stage tile in smem (stride TPAD), write transposed
    __syncthreads();                 // mainloop smem reads done before reuse
    float* S = sm;                   // 128 x TPAD floats (66 KB, fits in As+Bs)
#pragma unroll
    for (int mf = 0; mf < 4; ++mf)
#pragma unroll
        for (int nf = 0; nf < 4; ++nf){
            int r = m0w + mf*16 + grp;
            int c = n0w + nf*8 + 2*qc;
            S[r*TPAD + c]       = acc[mf][nf][0];
            S[r*TPAD + c + 1]   = acc[mf][nf][1];
            S[(r+8)*TPAD + c]   = acc[mf][nf][2];
            S[(r+8)*TPAD + c+1] = acc[mf][nf][3];
        }
    __syncthreads();

    float* outT = out + (size_t)(tn*128) * NN + (size_t)(tm*128);
    for (int rr = wid; rr < 128; rr += 8){
#pragma unroll
        for (int j = 0; j < 4; ++j){
            int c = j*32 + lane;
            outT[(size_t)rr*NN + c] = S[c*TPAD + rr];   // CF: (c+rr)%32 distinct
        }
    }
}

// ---------------- launcher ----------------
extern "C" void kernel_launch(void* const* d_in, const int* in_sizes, int n_in,
                              void* d_out, int out_size){
    const float* x  = (const float*)d_in[0];
    const int*   ei = (const int*)d_in[1];
    const float* W  = (const float*)d_in[2];
    const float* b  = (const float*)d_in[3];
    float*       out = (float*)d_out;

    int smem = 2*128*LDSW*4;  // 69632 B (>= 128*TPAD*4 staging)
    cudaFuncSetAttribute(k_xw,   cudaFuncAttributeMaxDynamicSharedMemorySize, smem);
    cudaFuncSetAttribute(k_gemm, cudaFuncAttributeMaxDynamicSharedMemorySize, smem);

    k_init   <<<(NN*NH + 255)/256, 256>>>();
    k_degree <<<(NE + 255)/256, 256>>>(ei);
    k_dinv   <<<(NN + 255)/256, 256>>>();
    k_xw     <<<NN/128, 256, smem>>>(x, W);
    k_scatter<<<(NE*32)/256, 256>>>(ei);
    k_final  <<<(NN*NH + 255)/256, 256>>>(b);
    k_gemm   <<<NTILES, 256, smem>>>(out);
}

// round 5
// speedup vs baseline: 2.2593x; 1.0329x over previous
#include <cuda_runtime.h>
#include <cstdint>

#define NN 16384
#define NH 128
#define NE (NN*32)

// ---------------- device scratch ----------------
__device__ __align__(16) float g_deg[NN];
__device__ __align__(16) float g_dinv[NN];
__device__ __align__(16) float g_h[NN*NH];     // x @ W
__device__ __align__(16) float g_agg[NN*NH];   // scatter accumulator
__device__ __align__(16) float g_h2[NN*NH];    // relu(gcn), tf32-rounded

#define KC 64
#define LDSW 68    // k_xw smem stride
#define KC2 32
#define LDS2 36    // k_gemm smem stride: (36r+c)%32 = (4r+c)%32 -> CF frag loads
#define TPAD 129   // transpose staging stride

__device__ __forceinline__ float tf32r(float v){
    uint32_t t; asm("cvt.rna.tf32.f32 %0, %1;" : "=r"(t) : "f"(v));
    return __uint_as_float(t);
}
__device__ __forceinline__ void cp16(float* dst, const float* src){
    uint32_t d = (uint32_t)__cvta_generic_to_shared(dst);
    asm volatile("cp.async.cg.shared.global [%0], [%1], 16;" :: "r"(d), "l"(src));
}
__device__ __forceinline__ void mma_tf32(float* d,
        uint32_t a0, uint32_t a1, uint32_t a2, uint32_t a3,
        uint32_t b0, uint32_t b1){
    asm volatile(
        "mma.sync.aligned.m16n8k8.row.col.f32.tf32.tf32.f32 "
        "{%0,%1,%2,%3}, {%4,%5,%6,%7}, {%8,%9}, {%0,%1,%2,%3};"
        : "+f"(d[0]), "+f"(d[1]), "+f"(d[2]), "+f"(d[3])
        : "r"(a0), "r"(a1), "r"(a2), "r"(a3), "r"(b0), "r"(b1));
}

// ---------------- stage 1: init ----------------
__global__ void k_init(){
    int i = blockIdx.x * blockDim.x + threadIdx.x;
    if (i < NN*NH) g_agg[i] = 0.0f;
    if (i < NN)    g_deg[i] = 1.0f;   // self-loop
}

// ---------------- stage 2: degree (edge_index is int32) ----------------
__global__ void k_degree(const int* __restrict__ ei){
    int e = blockIdx.x * blockDim.x + threadIdx.x;
    if (e >= NE) return;
    atomicAdd(&g_deg[ei[NE + e]], 1.0f);
}

// ---------------- stage 3: dinv ----------------
__global__ void k_dinv(){
    int i = blockIdx.x * blockDim.x + threadIdx.x;
    if (i < NN) g_dinv[i] = rsqrtf(g_deg[i]);
}

// ---------------- stage 4: h = x @ W via tf32 mma ----------------
__global__ void __launch_bounds__(256, 2) k_xw(const float* __restrict__ x,
                                               const float* __restrict__ W){
    extern __shared__ float sm[];
    float* As = sm;                  // 128 x LDSW
    float* Bs = sm + 128*LDSW;       // W^T chunk

    int tid  = threadIdx.x;
    int lane = tid & 31;
    int wid  = tid >> 5;
    int m0w  = (wid >> 2) * 64;
    int n0w  = (wid & 3) * 32;
    int row0 = blockIdx.x * 128;
    int grp  = lane >> 2, qc = lane & 3;

    float acc[4][4][4];
#pragma unroll
    for (int i = 0; i < 4; i++)
#pragma unroll
        for (int j = 0; j < 4; j++)
#pragma unroll
            for (int q = 0; q < 4; q++) acc[i][j][q] = 0.0f;

    for (int kc = 0; kc < 2; ++kc){
        if (kc) __syncthreads();
#pragma unroll
        for (int i = 0; i < 8; ++i){
            int idx = i*256 + tid;
            int r = idx >> 4, c4 = idx & 15;
            float4 v = *reinterpret_cast<const float4*>(x + (size_t)(row0 + r)*NH + kc*KC + c4*4);
            v.x = tf32r(v.x); v.y = tf32r(v.y); v.z = tf32r(v.z); v.w = tf32r(v.w);
            *reinterpret_cast<float4*>(As + r*LDSW + c4*4) = v;
        }
#pragma unroll
        for (int i = 0; i < 8; ++i){
            int idx = i*256 + tid;
            int n = idx & 127, kk4 = idx >> 7;
            float4 v;
            v.x = tf32r(W[(size_t)(kc*KC + kk4*4 + 0)*NH + n]);
            v.y = tf32r(W[(size_t)(kc*KC + kk4*4 + 1)*NH + n]);
            v.z = tf32r(W[(size_t)(kc*KC + kk4*4 + 2)*NH + n]);
            v.w = tf32r(W[(size_t)(kc*KC + kk4*4 + 3)*NH + n]);
            *reinterpret_cast<float4*>(Bs + n*LDSW + kk4*4) = v;
        }
        __syncthreads();

#pragma unroll
        for (int k8 = 0; k8 < KC/8; ++k8){
            int kb = k8*8;
            uint32_t a[4][4], b[4][2];
#pragma unroll
            for (int mf = 0; mf < 4; ++mf){
                int r0 = m0w + mf*16 + grp;
                a[mf][0] = __float_as_uint(As[r0*LDSW     + kb + qc]);
                a[mf][1] = __float_as_uint(As[(r0+8)*LDSW + kb + qc]);
                a[mf][2] = __float_as_uint(As[r0*LDSW     + kb + qc + 4]);
                a[mf][3] = __float_as_uint(As[(r0+8)*LDSW + kb + qc + 4]);
            }
#pragma unroll
            for (int nf = 0; nf < 4; ++nf){
                int rn = n0w + nf*8 + grp;
                b[nf][0] = __float_as_uint(Bs[rn*LDSW + kb + qc]);
                b[nf][1] = __float_as_uint(Bs[rn*LDSW + kb + qc + 4]);
            }
#pragma unroll
            for (int mf = 0; mf < 4; ++mf)
#pragma unroll
                for (int nf = 0; nf < 4; ++nf)
                    mma_tf32(acc[mf][nf], a[mf][0], a[mf][1], a[mf][2], a[mf][3],
                             b[nf][0], b[nf][1]);
        }
    }

#pragma unroll
    for (int mf = 0; mf < 4; ++mf)
#pragma unroll
        for (int nf = 0; nf < 4; ++nf){
            int r = m0w + mf*16 + grp;
            int c = n0w + nf*8 + 2*qc;
            *reinterpret_cast<float2*>(g_h + (size_t)(row0 + r)*NH + c) =
                make_float2(acc[mf][nf][0], acc[mf][nf][1]);
            *reinterpret_cast<float2*>(g_h + (size_t)(row0 + r + 8)*NH + c) =
                make_float2(acc[mf][nf][2], acc[mf][nf][3]);
        }
}

// ---------------- stage 5: edge scatter ----------------
__global__ void k_scatter(const int* __restrict__ ei){
    int g = blockIdx.x * blockDim.x + threadIdx.x;
    int e = g >> 5;
    if (e >= NE) return;
    int lane = g & 31;
    int r = ei[e];
    int c = ei[NE + e];
    float nrm = g_dinv[r] * g_dinv[c];
    float4 hv = *reinterpret_cast<const float4*>(g_h + (size_t)r*NH + lane*4);
    float4 v = make_float4(nrm*hv.x, nrm*hv.y, nrm*hv.z, nrm*hv.w);
    atomicAdd(reinterpret_cast<float4*>(g_agg + (size_t)c*NH + lane*4), v);
}

// ---------------- stage 6: self-loop + bias + relu + tf32 round -------------
__global__ void k_final(const float* __restrict__ b){
    int i = blockIdx.x * blockDim.x + threadIdx.x;
    if (i >= NN*NH) return;
    int n = i >> 7, c = i & 127;
    float di = g_dinv[n];
    float v = g_agg[i] + di*di*g_h[i] + b[c];
    g_h2[i] = tf32r(v > 0.0f ? v : 0.0f);
}

// ---------------- stage 7: C = H @ H^T, upper-triangle, cp.async pipeline ---
#define NTILES 8256   // 128*129/2
#define STG (2*128*LDS2)   // floats per stage (A+B)

__global__ void __launch_bounds__(256, 2) k_gemm(float* __restrict__ out){
    extern __shared__ float sm[];    // 3 stages x STG floats

    int tid  = threadIdx.x;
    int lane = tid & 31;
    int wid  = tid >> 5;
    int m0w  = (wid >> 2) * 64;
    int n0w  = (wid & 3) * 32;
    int grp  = lane >> 2, qc = lane & 3;

    int tm = 0, rem = blockIdx.x;
    while (rem >= 128 - tm){ rem -= 128 - tm; tm++; }
    int tn = tm + rem;

    const float* Ag = g_h2 + (size_t)tm * 128 * NH;
    const float* Bg = g_h2 + (size_t)tn * 128 * NH;

    // per-thread load coords: 4 float4 for A and 4 for B per chunk
    int lr[4], lc4[4];
#pragma unroll
    for (int i = 0; i < 4; ++i){
        int idx = i*256 + tid;
        lr[i] = idx >> 3; lc4[i] = idx & 7;
    }

#define PREFETCH(cidx, stage) do {                                         \
    float* Asp = sm + (stage)*STG;                                         \
    float* Bsp = Asp + 128*LDS2;                                           \
    _Pragma("unroll")                                                      \
    for (int i = 0; i < 4; ++i){                                           \
        cp16(Asp + lr[i]*LDS2 + lc4[i]*4, Ag + lr[i]*NH + (cidx)*KC2 + lc4[i]*4); \
        cp16(Bsp + lr[i]*LDS2 + lc4[i]*4, Bg + lr[i]*NH + (cidx)*KC2 + lc4[i]*4); \
    }                                                                      \
    asm volatile("cp.async.commit_group;");                                \
} while(0)

    float acc[4][4][4];
#pragma unroll
    for (int i = 0; i < 4; i++)
#pragma unroll
        for (int j = 0; j < 4; j++)
#pragma unroll
            for (int q = 0; q < 4; q++) acc[i][j][q] = 0.0f;

    PREFETCH(0, 0);
    PREFETCH(1, 1);

#pragma unroll
    for (int c = 0; c < 4; ++c){
        if (c < 3) asm volatile("cp.async.wait_group 1;");
        else       asm volatile("cp.async.wait_group 0;");
        __syncthreads();
        if (c + 2 < 4) PREFETCH(c + 2, (c + 2) % 3);

        float* As = sm + (c % 3)*STG;
        float* Bs = As + 128*LDS2;
#pragma unroll
        for (int k8 = 0; k8 < KC2/8; ++k8){
            int kb = k8*8;
            uint32_t a[4][4], b[4][2];
#pragma unroll
            for (int mf = 0; mf < 4; ++mf){
                int r0 = m0w + mf*16 + grp;
                a[mf][0] = __float_as_uint(As[r0*LDS2     + kb + qc]);
                a[mf][1] = __float_as_uint(As[(r0+8)*LDS2 + kb + qc]);
                a[mf][2] = __float_as_uint(As[r0*LDS2     + kb + qc + 4]);
                a[mf][3] = __float_as_uint(As[(r0+8)*LDS2 + kb + qc + 4]);
            }
#pragma unroll
            for (int nf = 0; nf < 4; ++nf){
                int rn = n0w + nf*8 + grp;
                b[nf][0] = __float_as_uint(Bs[rn*LDS2 + kb + qc]);
                b[nf][1] = __float_as_uint(Bs[rn*LDS2 + kb + qc + 4]);
            }
#pragma unroll
            for (int mf = 0; mf < 4; ++mf)
#pragma unroll
                for (int nf = 0; nf < 4; ++nf)
                    mma_tf32(acc[mf][nf], a[mf][0], a[mf][1], a[mf][2], a[mf][3],
                             b[nf][0], b[nf][1]);
        }
        __syncthreads();
    }

    // direct (coalesced) write of the (tm, tn) block
    float* outB = out + (size_t)(tm*128) * NN + (size_t)(tn*128);
#pragma unroll
    for (int mf = 0; mf < 4; ++mf)
#pragma unroll
        for (int nf = 0; nf < 4; ++nf){
            int r = m0w + mf*16 + grp;
            int c = n0w + nf*8 + 2*qc;
            *reinterpret_cast<float2*>(outB + (size_t)r*NN + c) =
                make_float2(acc[mf][nf][0], acc[mf][nf][1]);
            *reinterpret_cast<float2*>(outB + (size_t)(r+8)*NN + c) =
                make_float2(acc[mf][nf][2], acc[mf][nf][3]);
        }

    if (tm == tn) return;

    // mirrored (tn, tm) block: smem-staged transpose (CF both directions)
    float* S = sm;   // 128 x TPAD floats = 66048 B <= 110592 B
#pragma unroll
    for (int mf = 0; mf < 4; ++mf)
#pragma unroll
        for (int nf = 0; nf < 4; ++nf){
            int r = m0w + mf*16 + grp;
            int c = n0w + nf*8 + 2*qc;
            S[r*TPAD + c]       = acc[mf][nf][0];
            S[r*TPAD + c + 1]   = acc[mf][nf][1];
            S[(r+8)*TPAD + c]   = acc[mf][nf][2];
            S[(r+8)*TPAD + c+1] = acc[mf][nf][3];
        }
    __syncthreads();

    float* outT = out + (size_t)(tn*128) * NN + (size_t)(tm*128);
    for (int rr = wid; rr < 128; rr += 8){
#pragma unroll
        for (int j = 0; j < 4; ++j){
            int c = j*32 + lane;
            outT[(size_t)rr*NN + c] = S[c*TPAD + rr];
        }
    }
#undef PREFETCH
}

// ---------------- launcher ----------------
extern "C" void kernel_launch(void* const* d_in, const int* in_sizes, int n_in,
                              void* d_out, int out_size){
    const float* x  = (const float*)d_in[0];
    const int*   ei = (const int*)d_in[1];
    const float* W  = (const float*)d_in[2];
    const float* b  = (const float*)d_in[3];
    float*       out = (float*)d_out;

    int smem_xw   = 2*128*LDSW*4;       // 69632 B
    int smem_gemm = 3*STG*4;            // 110592 B (3-stage pipeline)
    cudaFuncSetAttribute(k_xw,   cudaFuncAttributeMaxDynamicSharedMemorySize, smem_xw);
    cudaFuncSetAttribute(k_gemm, cudaFuncAttributeMaxDynamicSharedMemorySize, smem_gemm);

    k_init   <<<(NN*NH + 255)/256, 256>>>();
    k_degree <<<(NE + 255)/256, 256>>>(ei);
    k_dinv   <<<(NN + 255)/256, 256>>>();
    k_xw     <<<NN/128, 256, smem_xw>>>(x, W);
    k_scatter<<<(NE*32)/256, 256>>>(ei);
    k_final  <<<(NN*NH + 255)/256, 256>>>(b);
    k_gemm   <<<NTILES, 256, smem_gemm>>>(out);
}